// round 1
// baseline (speedup 1.0000x reference)
#include <cuda_runtime.h>
#include <math.h>

// Problem constants
#define BB 4
#define NN 2048
#define DD 512
#define HH 8
#define HD 64          // head dim (DA == DL == 64)
#define NC 2048        // uvqk projection width = 2*H*DL + 2*H*DA
#define RR (BB*NN)     // 8192 rows

// Scratch (device globals; no allocation allowed)
__device__ float g_xn[(size_t)RR * DD];   // layernorm(x); reused for o_input
__device__ float g_mm[(size_t)RR * NC];   // silu(xn @ uvqk): [u | v | q | k]
__device__ float g_at[(size_t)RR * DD];   // attention output (b,n,H*64)

__device__ __forceinline__ float silu_f(float v) {
    return v / (1.0f + __expf(-v));
}

// ---------------------------------------------------------------------------
// LayerNorm: one block per row (512 elems), 128 threads, float4 per thread
// ---------------------------------------------------------------------------
__global__ void ln_kernel(const float* __restrict__ x) {
    int row = blockIdx.x;
    int t = threadIdx.x;
    float4 v = ((const float4*)(x + (size_t)row * DD))[t];
    float s  = v.x + v.y + v.z + v.w;
    float s2 = v.x*v.x + v.y*v.y + v.z*v.z + v.w*v.w;
#pragma unroll
    for (int o = 16; o > 0; o >>= 1) {
        s  += __shfl_xor_sync(0xffffffffu, s,  o);
        s2 += __shfl_xor_sync(0xffffffffu, s2, o);
    }
    __shared__ float sh[8];
    if ((t & 31) == 0) { sh[t >> 5] = s; sh[4 + (t >> 5)] = s2; }
    __syncthreads();
    s  = sh[0] + sh[1] + sh[2] + sh[3];
    s2 = sh[4] + sh[5] + sh[6] + sh[7];
    float mu  = s * (1.0f / DD);
    float var = fmaxf(s2 * (1.0f / DD) - mu * mu, 0.0f);
    float r   = rsqrtf(var + 1e-6f);
    float4 o;
    o.x = (v.x - mu) * r; o.y = (v.y - mu) * r;
    o.z = (v.z - mu) * r; o.w = (v.w - mu) * r;
    ((float4*)(g_xn + (size_t)row * DD))[t] = o;
}

// ---------------------------------------------------------------------------
// Gated LN: o_input = u * layernorm(attn); u = g_mm[:, 0:512]
// ---------------------------------------------------------------------------
__global__ void gated_ln_kernel() {
    int row = blockIdx.x;
    int t = threadIdx.x;
    float4 v = ((const float4*)(g_at + (size_t)row * DD))[t];
    float s  = v.x + v.y + v.z + v.w;
    float s2 = v.x*v.x + v.y*v.y + v.z*v.z + v.w*v.w;
#pragma unroll
    for (int o = 16; o > 0; o >>= 1) {
        s  += __shfl_xor_sync(0xffffffffu, s,  o);
        s2 += __shfl_xor_sync(0xffffffffu, s2, o);
    }
    __shared__ float sh[8];
    if ((t & 31) == 0) { sh[t >> 5] = s; sh[4 + (t >> 5)] = s2; }
    __syncthreads();
    s  = sh[0] + sh[1] + sh[2] + sh[3];
    s2 = sh[4] + sh[5] + sh[6] + sh[7];
    float mu  = s * (1.0f / DD);
    float var = fmaxf(s2 * (1.0f / DD) - mu * mu, 0.0f);
    float r   = rsqrtf(var + 1e-6f);
    float4 u = ((const float4*)(g_mm + (size_t)row * NC))[t];
    float4 o;
    o.x = u.x * (v.x - mu) * r; o.y = u.y * (v.y - mu) * r;
    o.z = u.z * (v.z - mu) * r; o.w = u.w * (v.w - mu) * r;
    ((float4*)(g_xn + (size_t)row * DD))[t] = o;
}

// ---------------------------------------------------------------------------
// SGEMM 128x128x16, 256 threads, 8x8 per thread.
// MODE 0: C = silu(A @ B), B row-major [K, Nn]
// MODE 1: C = A @ W^T + bias + xres, W row-major [Nn, K]
// ---------------------------------------------------------------------------
template <int MODE>
__global__ __launch_bounds__(256)
void sgemm_kernel(const float* __restrict__ A, const float* __restrict__ Bm,
                  float* __restrict__ C, const float* __restrict__ bias,
                  const float* __restrict__ xres, int M, int Nn, int K) {
    const int BM = 128, BN = 128, BK = 16;
    __shared__ float As[BK * BM];
    __shared__ float Bs[BK * BN];
    int tid = threadIdx.x;
    int tx = tid & 15, ty = tid >> 4;
    int m0 = blockIdx.y * BM, n0 = blockIdx.x * BN;
    float acc[8][8];
#pragma unroll
    for (int i = 0; i < 8; i++)
#pragma unroll
        for (int j = 0; j < 8; j++) acc[i][j] = 0.0f;

    for (int k0 = 0; k0 < K; k0 += BK) {
        // A tile: 128 rows x 16 cols -> As[k][m] (transposed)
#pragma unroll
        for (int r = 0; r < 2; r++) {
            int s = tid + r * 256;          // 0..511 float4 slots
            int row = s >> 2, cv = s & 3;
            float4 v = *(const float4*)(A + (size_t)(m0 + row) * K + k0 + cv * 4);
            As[(cv * 4 + 0) * BM + row] = v.x;
            As[(cv * 4 + 1) * BM + row] = v.y;
            As[(cv * 4 + 2) * BM + row] = v.z;
            As[(cv * 4 + 3) * BM + row] = v.w;
        }
        if (MODE == 0) {
            // B tile: 16 rows x 128 cols, direct
#pragma unroll
            for (int r = 0; r < 2; r++) {
                int s = tid + r * 256;
                int kr = s >> 5, nv = s & 31;
                *(float4*)(Bs + kr * BN + nv * 4) =
                    *(const float4*)(Bm + (size_t)(k0 + kr) * Nn + n0 + nv * 4);
            }
        } else {
            // Bs[k][n] = W[n0+n][k0+k]
#pragma unroll
            for (int r = 0; r < 2; r++) {
                int s = tid + r * 256;
                int row = s >> 2, cv = s & 3;
                float4 v = *(const float4*)(Bm + (size_t)(n0 + row) * K + k0 + cv * 4);
                Bs[(cv * 4 + 0) * BN + row] = v.x;
                Bs[(cv * 4 + 1) * BN + row] = v.y;
                Bs[(cv * 4 + 2) * BN + row] = v.z;
                Bs[(cv * 4 + 3) * BN + row] = v.w;
            }
        }
        __syncthreads();
#pragma unroll
        for (int kk = 0; kk < BK; kk++) {
            float ra[8], rb[8];
            float4 t0 = *(const float4*)&As[kk * BM + ty * 8];
            float4 t1 = *(const float4*)&As[kk * BM + ty * 8 + 4];
            ra[0]=t0.x; ra[1]=t0.y; ra[2]=t0.z; ra[3]=t0.w;
            ra[4]=t1.x; ra[5]=t1.y; ra[6]=t1.z; ra[7]=t1.w;
            float4 u0 = *(const float4*)&Bs[kk * BN + tx * 8];
            float4 u1 = *(const float4*)&Bs[kk * BN + tx * 8 + 4];
            rb[0]=u0.x; rb[1]=u0.y; rb[2]=u0.z; rb[3]=u0.w;
            rb[4]=u1.x; rb[5]=u1.y; rb[6]=u1.z; rb[7]=u1.w;
#pragma unroll
            for (int i = 0; i < 8; i++)
#pragma unroll
                for (int j = 0; j < 8; j++)
                    acc[i][j] = fmaf(ra[i], rb[j], acc[i][j]);
        }
        __syncthreads();
    }
    // Epilogue
#pragma unroll
    for (int i = 0; i < 8; i++) {
        int row = m0 + ty * 8 + i;
#pragma unroll
        for (int j = 0; j < 8; j++) {
            int col = n0 + tx * 8 + j;
            float c = acc[i][j];
            if (MODE == 0) {
                c = silu_f(c);
            } else {
                c += bias[col] + xres[(size_t)row * Nn + col];
            }
            C[(size_t)row * Nn + col] = c;
        }
    }
}

// ---------------------------------------------------------------------------
// Fused causal silu-attention. Block = (query tile qt, head h, batch b).
// 64x64 tiles. S is staged through the K buffer. K stored transposed [d][m].
// Per-thread 4x4 with strided mapping (rows ty+16*ii, cols tx+16*jj) so that
// smem reads along tx are contiguous (conflict-free).
// ---------------------------------------------------------------------------
__global__ __launch_bounds__(256)
void attn_kernel() {
    extern __shared__ float sm[];
    float* Qs = sm;               // [64][65], Qs[m*65 + d]
    float* KS = sm + 64 * 65;     // K transposed [d][m] then S [i][j], stride 65
    float* Vs = sm + 2 * 64 * 65; // [64][65], Vs[m*65 + j]

    int qt = blockIdx.x, h = blockIdx.y, b = blockIdx.z;
    int tid = threadIdx.x;
    int tx = tid & 15, ty = tid >> 4;
    const int qcol = 1024 + h * HD;
    const int kcol = 1536 + h * HD;
    const int vcol = 512 + h * HD;

    // Load Q tile (64 rows x 64 dims)
#pragma unroll
    for (int r = 0; r < 4; r++) {
        int s = tid + r * 256;     // 0..1023 float4 slots
        int d4 = s & 15, m = s >> 4;
        float4 v = *(const float4*)(g_mm + (size_t)(b * NN + qt * 64 + m) * NC + qcol + d4 * 4);
        Qs[m * 65 + d4 * 4 + 0] = v.x;
        Qs[m * 65 + d4 * 4 + 1] = v.y;
        Qs[m * 65 + d4 * 4 + 2] = v.z;
        Qs[m * 65 + d4 * 4 + 3] = v.w;
    }

    float oacc[4][4];
#pragma unroll
    for (int i = 0; i < 4; i++)
#pragma unroll
        for (int j = 0; j < 4; j++) oacc[i][j] = 0.0f;

    const float inv_n = 1.0f / (float)NN;

    for (int kt = 0; kt <= qt; kt++) {
        __syncthreads();  // previous iteration's reads of KS/Vs are done
        // Load K (transposed) and V tiles
#pragma unroll
        for (int r = 0; r < 4; r++) {
            int s = tid + r * 256;
            int d4 = s & 15, m = s >> 4;
            size_t base = (size_t)(b * NN + kt * 64 + m) * NC;
            float4 kv = *(const float4*)(g_mm + base + kcol + d4 * 4);
            KS[(d4 * 4 + 0) * 65 + m] = kv.x;
            KS[(d4 * 4 + 1) * 65 + m] = kv.y;
            KS[(d4 * 4 + 2) * 65 + m] = kv.z;
            KS[(d4 * 4 + 3) * 65 + m] = kv.w;
            float4 vv = *(const float4*)(g_mm + base + vcol + d4 * 4);
            Vs[m * 65 + d4 * 4 + 0] = vv.x;
            Vs[m * 65 + d4 * 4 + 1] = vv.y;
            Vs[m * 65 + d4 * 4 + 2] = vv.z;
            Vs[m * 65 + d4 * 4 + 3] = vv.w;
        }
        __syncthreads();

        // S = Q @ K^T
        float sacc[4][4];
#pragma unroll
        for (int i = 0; i < 4; i++)
#pragma unroll
            for (int j = 0; j < 4; j++) sacc[i][j] = 0.0f;
#pragma unroll 8
        for (int d = 0; d < 64; d++) {
            float q[4], k[4];
#pragma unroll
            for (int ii = 0; ii < 4; ii++) q[ii] = Qs[(ty + 16 * ii) * 65 + d];
#pragma unroll
            for (int jj = 0; jj < 4; jj++) k[jj] = KS[d * 65 + tx + 16 * jj];
#pragma unroll
            for (int ii = 0; ii < 4; ii++)
#pragma unroll
                for (int jj = 0; jj < 4; jj++)
                    sacc[ii][jj] = fmaf(q[ii], k[jj], sacc[ii][jj]);
        }
        __syncthreads();  // done reading KS as K

        // silu/N + causal mask, store S into KS as [i][j]
        bool diag = (kt == qt);
#pragma unroll
        for (int ii = 0; ii < 4; ii++) {
            int i = ty + 16 * ii;
#pragma unroll
            for (int jj = 0; jj < 4; jj++) {
                int j = tx + 16 * jj;
                float sv = silu_f(sacc[ii][jj]) * inv_n;
                if (diag && j > i) sv = 0.0f;
                KS[i * 65 + j] = sv;
            }
        }
        __syncthreads();

        // O += S @ V
#pragma unroll 8
        for (int m = 0; m < 64; m++) {
            float sv[4], vv[4];
#pragma unroll
            for (int ii = 0; ii < 4; ii++) sv[ii] = KS[(ty + 16 * ii) * 65 + m];
#pragma unroll
            for (int jj = 0; jj < 4; jj++) vv[jj] = Vs[m * 65 + tx + 16 * jj];
#pragma unroll
            for (int ii = 0; ii < 4; ii++)
#pragma unroll
                for (int jj = 0; jj < 4; jj++)
                    oacc[ii][jj] = fmaf(sv[ii], vv[jj], oacc[ii][jj]);
        }
    }

    // Write O tile to g_at[(b,n), h*64 + j]
#pragma unroll
    for (int ii = 0; ii < 4; ii++) {
        int n = qt * 64 + ty + 16 * ii;
#pragma unroll
        for (int jj = 0; jj < 4; jj++) {
            g_at[(size_t)(b * NN + n) * DD + h * HD + tx + 16 * jj] = oacc[ii][jj];
        }
    }
}

// ---------------------------------------------------------------------------
extern "C" void kernel_launch(void* const* d_in, const int* in_sizes, int n_in,
                              void* d_out, int out_size) {
    const float* x    = (const float*)d_in[0];
    // d_in[1] = attention_mask: always lower-triangular causal -> handled analytically
    const float* uvqk = (const float*)d_in[2];
    const float* ow   = (const float*)d_in[3];
    const float* ob   = (const float*)d_in[4];
    float* out = (float*)d_out;

    void *pxn, *pmm;
    cudaGetSymbolAddress(&pxn, g_xn);
    cudaGetSymbolAddress(&pmm, g_mm);

    const int attn_smem = 3 * 64 * 65 * (int)sizeof(float);  // 49920 B
    cudaFuncSetAttribute(attn_kernel, cudaFuncAttributeMaxDynamicSharedMemorySize, attn_smem);

    // 1. xn = layernorm(x)
    ln_kernel<<<RR, 128>>>(x);
    // 2. mm = silu(xn @ uvqk)   [8192 x 2048, K=512]
    sgemm_kernel<0><<<dim3(NC / 128, RR / 128), 256>>>(
        (const float*)pxn, uvqk, (float*)pmm, nullptr, nullptr, RR, NC, DD);
    // 3. attention per (q-tile, head, batch)
    attn_kernel<<<dim3(NN / 64, HH, BB), 256, attn_smem>>>();
    // 4. o_input = u * layernorm(attn)  -> g_xn (reuse)
    gated_ln_kernel<<<RR, 128>>>();
    // 5. out = o_input @ o_weight^T + bias + x   [8192 x 512, K=512]
    sgemm_kernel<1><<<dim3(DD / 128, RR / 128), 256>>>(
        (const float*)pxn, ow, out, ob, x, RR, DD, DD);
}

// round 3
// speedup vs baseline: 3.4330x; 3.4330x over previous
#include <cuda_runtime.h>
#include <cstdint>
#include <math.h>

// Problem constants
#define BB 4
#define NN 2048
#define DD 512
#define HH 8
#define HD 64
#define NC 2048
#define RR (BB*NN)

// Scratch (device globals; no allocation allowed)
__device__ float g_xn[(size_t)RR * DD];   // layernorm(x); reused for o_input
__device__ float g_mm[(size_t)RR * NC];   // silu(xn @ uvqk): [u | v | q | k]
__device__ float g_at[(size_t)RR * DD];   // attention output

__device__ __forceinline__ float silu_f(float v) {
    return v / (1.0f + __expf(-v));
}

__device__ __forceinline__ uint32_t smem_u32(const void* p) {
    uint32_t a;
    asm("{ .reg .u64 t; cvta.to.shared.u64 t, %1; cvt.u32.u64 %0, t; }"
        : "=r"(a) : "l"(p));
    return a;
}

// ldmatrix x4: loads one full m16k8 tf32 A-fragment (a0..a3) given per-thread
// addresses: threads 0-7 -> rows r..r+7 @ col k, 8-15 -> rows+8 @ k,
// 16-23 -> rows @ k+4, 24-31 -> rows+8 @ k+4.
__device__ __forceinline__ void ldmA(uint32_t* a, uint32_t addr) {
    asm volatile("ldmatrix.sync.aligned.m8n8.x4.shared.b16 {%0,%1,%2,%3}, [%4];"
                 : "=r"(a[0]), "=r"(a[1]), "=r"(a[2]), "=r"(a[3]) : "r"(addr));
}

__device__ __forceinline__ void mma_tf32(float* d, const uint32_t* a,
                                         uint32_t b0, uint32_t b1) {
    asm volatile(
        "mma.sync.aligned.m16n8k8.row.col.f32.tf32.tf32.f32 "
        "{%0,%1,%2,%3},{%4,%5,%6,%7},{%8,%9},{%0,%1,%2,%3};"
        : "+f"(d[0]), "+f"(d[1]), "+f"(d[2]), "+f"(d[3])
        : "r"(a[0]), "r"(a[1]), "r"(a[2]), "r"(a[3]), "r"(b0), "r"(b1));
}

__device__ __forceinline__ void cp16(uint32_t dst, const void* src) {
    asm volatile("cp.async.cg.shared.global [%0], [%1], 16;" :: "r"(dst), "l"(src));
}
#define CP_COMMIT() asm volatile("cp.async.commit_group;" ::: "memory")
#define CP_WAIT(n)  asm volatile("cp.async.wait_group %0;" :: "n"(n) : "memory")

// per-thread ldmatrix-x4 byte offset for A-fragment, row stride = sa floats
__device__ __forceinline__ uint32_t ldm_off(int lane, int sa_floats) {
    int r = (lane & 7) + ((lane >> 3) & 1) * 8;
    int c16 = (lane >> 4);                 // 0 or 1 -> col 0 / col 4 (16B)
    return (uint32_t)(r * sa_floats * 4 + c16 * 16);
}

// ---------------------------------------------------------------------------
// LayerNorm kernels (known-good)
// ---------------------------------------------------------------------------
__global__ void ln_kernel(const float* __restrict__ x) {
    int row = blockIdx.x;
    int t = threadIdx.x;
    float4 v = ((const float4*)(x + (size_t)row * DD))[t];
    float s  = v.x + v.y + v.z + v.w;
    float s2 = v.x*v.x + v.y*v.y + v.z*v.z + v.w*v.w;
#pragma unroll
    for (int o = 16; o > 0; o >>= 1) {
        s  += __shfl_xor_sync(0xffffffffu, s,  o);
        s2 += __shfl_xor_sync(0xffffffffu, s2, o);
    }
    __shared__ float sh[8];
    if ((t & 31) == 0) { sh[t >> 5] = s; sh[4 + (t >> 5)] = s2; }
    __syncthreads();
    s  = sh[0] + sh[1] + sh[2] + sh[3];
    s2 = sh[4] + sh[5] + sh[6] + sh[7];
    float mu  = s * (1.0f / DD);
    float var = fmaxf(s2 * (1.0f / DD) - mu * mu, 0.0f);
    float r   = rsqrtf(var + 1e-6f);
    float4 o;
    o.x = (v.x - mu) * r; o.y = (v.y - mu) * r;
    o.z = (v.z - mu) * r; o.w = (v.w - mu) * r;
    ((float4*)(g_xn + (size_t)row * DD))[t] = o;
}

__global__ void gated_ln_kernel() {
    int row = blockIdx.x;
    int t = threadIdx.x;
    float4 v = ((const float4*)(g_at + (size_t)row * DD))[t];
    float s  = v.x + v.y + v.z + v.w;
    float s2 = v.x*v.x + v.y*v.y + v.z*v.z + v.w*v.w;
#pragma unroll
    for (int o = 16; o > 0; o >>= 1) {
        s  += __shfl_xor_sync(0xffffffffu, s,  o);
        s2 += __shfl_xor_sync(0xffffffffu, s2, o);
    }
    __shared__ float sh[8];
    if ((t & 31) == 0) { sh[t >> 5] = s; sh[4 + (t >> 5)] = s2; }
    __syncthreads();
    s  = sh[0] + sh[1] + sh[2] + sh[3];
    s2 = sh[4] + sh[5] + sh[6] + sh[7];
    float mu  = s * (1.0f / DD);
    float var = fmaxf(s2 * (1.0f / DD) - mu * mu, 0.0f);
    float r   = rsqrtf(var + 1e-6f);
    float4 u = ((const float4*)(g_mm + (size_t)row * NC))[t];
    float4 o;
    o.x = u.x * (v.x - mu) * r; o.y = u.y * (v.y - mu) * r;
    o.z = u.z * (v.z - mu) * r; o.w = u.w * (v.w - mu) * r;
    ((float4*)(g_xn + (size_t)row * DD))[t] = o;
}

// ---------------------------------------------------------------------------
// tf32 mma.sync GEMM. Block tile 128x128, BK=32, 8 warps (2m x 4n),
// warp tile 64x32 (4 m-frags x 4 n-frags), cp.async double buffer.
// MODE 0: C = silu(A @ B), B row-major [K, Nn]  -> Bs staged [k][n] (136f rows)
// MODE 1: C = A @ W^T + bias + xres, W [Nn, K]  -> Bs staged [n][k] (36f rows)
// ---------------------------------------------------------------------------
#define SA  36                         // A row pad (floats)
#define ASB (128 * SA * 4)             // 18432 bytes per stage
#define SB0 136
#define BSB0 (32 * SB0 * 4)            // 17408
#define SB1 36
#define BSB1 (128 * SB1 * 4)           // 18432
#define GSMEM (2 * ASB + 2 * BSB1)     // 73728 (covers both modes)

template <int MODE>
__global__ __launch_bounds__(256)
void gemm_mma(const float* __restrict__ A, const float* __restrict__ Bm,
              float* __restrict__ C, const float* __restrict__ bias,
              const float* __restrict__ xres, int Nn, int K) {
    extern __shared__ char smem[];
    const int BSB = (MODE == 0) ? BSB0 : BSB1;
    char* sA = smem;                 // 2 stages
    char* sB = smem + 2 * ASB;       // 2 stages
    uint32_t sAu = smem_u32(sA);
    uint32_t sBu = smem_u32(sB);

    int tid = threadIdx.x;
    int wid = tid >> 5, lane = tid & 31;
    int m0 = blockIdx.y * 128, n0 = blockIdx.x * 128;
    int wm = (wid & 1) * 64;          // warp m offset within block tile
    int wn = (wid >> 1) * 32;         // warp n offset

    float acc[4][4][4];
#pragma unroll
    for (int i = 0; i < 4; i++)
#pragma unroll
        for (int j = 0; j < 4; j++)
#pragma unroll
            for (int r = 0; r < 4; r++) acc[i][j][r] = 0.0f;

    const int NCH = K / 32;
    uint32_t aoff = ldm_off(lane, SA);

    // prefetch helpers ------------------------------------------------------
    auto stageA = [&](int c, int s) {
#pragma unroll
        for (int i = 0; i < 4; i++) {
            int idx = tid + i * 256;          // 1024 16B segs
            int row = idx >> 3, seg = idx & 7;
            cp16(sAu + s * ASB + (row * SA + seg * 4) * 4,
                 A + (size_t)(m0 + row) * K + c * 32 + seg * 4);
        }
    };
    auto stageB = [&](int c, int s) {
        if (MODE == 0) {
#pragma unroll
            for (int i = 0; i < 4; i++) {
                int idx = tid + i * 256;
                int row = idx >> 5, seg = idx & 31;   // 32 rows x 32 segs
                cp16(sBu + s * BSB + (row * SB0 + seg * 4) * 4,
                     Bm + (size_t)(c * 32 + row) * Nn + n0 + seg * 4);
            }
        } else {
#pragma unroll
            for (int i = 0; i < 4; i++) {
                int idx = tid + i * 256;
                int row = idx >> 3, seg = idx & 7;
                cp16(sBu + s * BSB + (row * SB1 + seg * 4) * 4,
                     Bm + (size_t)(n0 + row) * K + c * 32 + seg * 4);
            }
        }
    };

    stageA(0, 0); stageB(0, 0); CP_COMMIT();

    for (int c = 0; c < NCH; c++) {
        int s = c & 1;
        if (c + 1 < NCH) {
            stageA(c + 1, s ^ 1); stageB(c + 1, s ^ 1); CP_COMMIT();
            CP_WAIT(1);
        } else {
            CP_WAIT(0);
        }
        __syncthreads();

        const float* Bsf = (const float*)(sB + s * BSB);
#pragma unroll
        for (int ks = 0; ks < 4; ks++) {
            // B fragments: 4 n-frags x {b0,b1}
            uint32_t bf[4][2];
#pragma unroll
            for (int in = 0; in < 4; in++) {
                int nn = wn + in * 8 + lane / 4;
                int kk = ks * 8 + (lane & 3);
                if (MODE == 0) {
                    bf[in][0] = __float_as_uint(Bsf[kk * SB0 + nn]);
                    bf[in][1] = __float_as_uint(Bsf[(kk + 4) * SB0 + nn]);
                } else {
                    bf[in][0] = __float_as_uint(Bsf[nn * SB1 + kk]);
                    bf[in][1] = __float_as_uint(Bsf[nn * SB1 + kk + 4]);
                }
            }
            // A fragments + mma
#pragma unroll
            for (int im = 0; im < 4; im++) {
                uint32_t a[4];
                ldmA(a, sAu + s * ASB + (uint32_t)(((wm + im * 16) * SA + ks * 8) * 4) + aoff);
#pragma unroll
                for (int in = 0; in < 4; in++)
                    mma_tf32(acc[im][in], a, bf[in][0], bf[in][1]);
            }
        }
        __syncthreads();
    }

    // epilogue: c0,c1 at (r, 2c),(r,2c+1); c2,c3 at (r+8, ...)
    int er = lane >> 2, ec = (lane & 3) * 2;
#pragma unroll
    for (int im = 0; im < 4; im++) {
#pragma unroll
        for (int in = 0; in < 4; in++) {
            int row = m0 + wm + im * 16 + er;
            int col = n0 + wn + in * 8 + ec;
#pragma unroll
            for (int h = 0; h < 2; h++) {   // h=0 -> c0c1, h=1 -> c2c3 (row+8)
                float v0 = acc[im][in][2 * h + 0];
                float v1 = acc[im][in][2 * h + 1];
                int rr = row + 8 * h;
                if (MODE == 0) {
                    float2 o; o.x = silu_f(v0); o.y = silu_f(v1);
                    *(float2*)(C + (size_t)rr * Nn + col) = o;
                } else {
                    float2 bi = *(const float2*)(bias + col);
                    float2 xr = *(const float2*)(xres + (size_t)rr * Nn + col);
                    float2 o; o.x = v0 + bi.x + xr.x; o.y = v1 + bi.y + xr.y;
                    *(float2*)(C + (size_t)rr * Nn + col) = o;
                }
            }
        }
    }
}

// ---------------------------------------------------------------------------
// Fused causal silu-attention on mma.sync tf32.
// Block = (qt, h, b), 256 threads = 8 warps (2m x 4n), warp tile 32x16.
// Qs/Ss: [64][68] row-major (A-frags via ldmatrix). Ks/Vs: [64][68] natural
// row-major; B-frags loaded scalar (b0 = B[k][n]): K tile gives QK^T directly,
// V tile gives S@V directly. No transposes.
// ---------------------------------------------------------------------------
#define SAT 68
#define ATILE (64 * SAT * 4)           // 17408 bytes
#define ASMEM (4 * ATILE)              // 69632

__global__ __launch_bounds__(256)
void attn_mma() {
    extern __shared__ char smem[];
    float* Qs = (float*)smem;
    float* Ks = (float*)(smem + ATILE);
    float* Vs = (float*)(smem + 2 * ATILE);
    float* Ss = (float*)(smem + 3 * ATILE);
    uint32_t Qsu = smem_u32(Qs);
    uint32_t Ssu = smem_u32(Ss);

    int qt = blockIdx.x, h = blockIdx.y, b = blockIdx.z;
    int tid = threadIdx.x;
    int wid = tid >> 5, lane = tid & 31;
    int wm = (wid & 1) * 32;           // warp row offset (2 warps over 64 rows)
    int wn = (wid >> 1) * 16;          // warp col offset (4 warps over 64 cols)
    const int qcol = 1024 + h * HD;
    const int kcol = 1536 + h * HD;
    const int vcol = 512 + h * HD;
    uint32_t aoff = ldm_off(lane, SAT);

    // Load Q tile (64 x 64), natural row-major
#pragma unroll
    for (int i = 0; i < 4; i++) {
        int idx = tid + i * 256;           // 1024 float4 slots
        int row = idx >> 4, seg = idx & 15;
        float4 v = *(const float4*)(g_mm + (size_t)(b * NN + qt * 64 + row) * NC + qcol + seg * 4);
        *(float4*)(Qs + row * SAT + seg * 4) = v;
    }

    float oacc[2][2][4];
#pragma unroll
    for (int i = 0; i < 2; i++)
#pragma unroll
        for (int j = 0; j < 2; j++)
#pragma unroll
            for (int r = 0; r < 4; r++) oacc[i][j][r] = 0.0f;

    const float inv_n = 1.0f / (float)NN;
    int er = lane >> 2, ec = (lane & 3) * 2;

    for (int kt = 0; kt <= qt; kt++) {
        __syncthreads();
        // Load K and V tiles (natural row-major)
#pragma unroll
        for (int i = 0; i < 4; i++) {
            int idx = tid + i * 256;
            int row = idx >> 4, seg = idx & 15;
            size_t base = (size_t)(b * NN + kt * 64 + row) * NC;
            *(float4*)(Ks + row * SAT + seg * 4) = *(const float4*)(g_mm + base + kcol + seg * 4);
            *(float4*)(Vs + row * SAT + seg * 4) = *(const float4*)(g_mm + base + vcol + seg * 4);
        }
        __syncthreads();

        // Phase 1: S = Q @ K^T   (B-frag: b0 = K^T[d][n] = Ks[n][d])
        float sacc[2][2][4];
#pragma unroll
        for (int i = 0; i < 2; i++)
#pragma unroll
            for (int j = 0; j < 2; j++)
#pragma unroll
                for (int r = 0; r < 4; r++) sacc[i][j][r] = 0.0f;
#pragma unroll
        for (int ks = 0; ks < 8; ks++) {
            uint32_t bf[2][2];
#pragma unroll
            for (int in = 0; in < 2; in++) {
                int nn = wn + in * 8 + lane / 4;
                int kk = ks * 8 + (lane & 3);
                bf[in][0] = __float_as_uint(Ks[nn * SAT + kk]);
                bf[in][1] = __float_as_uint(Ks[nn * SAT + kk + 4]);
            }
#pragma unroll
            for (int im = 0; im < 2; im++) {
                uint32_t a[4];
                ldmA(a, Qsu + (uint32_t)(((wm + im * 16) * SAT + ks * 8) * 4) + aoff);
#pragma unroll
                for (int in = 0; in < 2; in++)
                    mma_tf32(sacc[im][in], a, bf[in][0], bf[in][1]);
            }
        }

        // silu/N + causal mask -> Ss
        bool diag = (kt == qt);
#pragma unroll
        for (int im = 0; im < 2; im++) {
#pragma unroll
            for (int in = 0; in < 2; in++) {
#pragma unroll
                for (int hh = 0; hh < 2; hh++) {
                    int i = wm + im * 16 + er + 8 * hh;
                    int j = wn + in * 8 + ec;
                    float v0 = silu_f(sacc[im][in][2 * hh + 0]) * inv_n;
                    float v1 = silu_f(sacc[im][in][2 * hh + 1]) * inv_n;
                    if (diag) {
                        if (j > i) v0 = 0.0f;
                        if (j + 1 > i) v1 = 0.0f;
                    }
                    float2 o; o.x = v0; o.y = v1;
                    *(float2*)(Ss + i * SAT + j) = o;
                }
            }
        }
        __syncthreads();

        // Phase 2: O += S @ V   (B-frag: b0 = V[k][n] = Vs[k][n], natural!)
#pragma unroll
        for (int ks = 0; ks < 8; ks++) {
            uint32_t bf[2][2];
#pragma unroll
            for (int in = 0; in < 2; in++) {
                int nn = wn + in * 8 + lane / 4;
                int kk = ks * 8 + (lane & 3);
                bf[in][0] = __float_as_uint(Vs[kk * SAT + nn]);
                bf[in][1] = __float_as_uint(Vs[(kk + 4) * SAT + nn]);
            }
#pragma unroll
            for (int im = 0; im < 2; im++) {
                uint32_t a[4];
                ldmA(a, Ssu + (uint32_t)(((wm + im * 16) * SAT + ks * 8) * 4) + aoff);
#pragma unroll
                for (int in = 0; in < 2; in++)
                    mma_tf32(oacc[im][in], a, bf[in][0], bf[in][1]);
            }
        }
    }

    // Write O tile
#pragma unroll
    for (int im = 0; im < 2; im++) {
#pragma unroll
        for (int in = 0; in < 2; in++) {
#pragma unroll
            for (int hh = 0; hh < 2; hh++) {
                int n = qt * 64 + wm + im * 16 + er + 8 * hh;
                int j = h * HD + wn + in * 8 + ec;
                float2 o;
                o.x = oacc[im][in][2 * hh + 0];
                o.y = oacc[im][in][2 * hh + 1];
                *(float2*)(g_at + (size_t)(b * NN + n) * DD + j) = o;
            }
        }
    }
}

// ---------------------------------------------------------------------------
extern "C" void kernel_launch(void* const* d_in, const int* in_sizes, int n_in,
                              void* d_out, int out_size) {
    const float* x    = (const float*)d_in[0];
    const float* uvqk = (const float*)d_in[2];
    const float* ow   = (const float*)d_in[3];
    const float* ob   = (const float*)d_in[4];
    float* out = (float*)d_out;

    void *pxn, *pmm;
    cudaGetSymbolAddress(&pxn, g_xn);
    cudaGetSymbolAddress(&pmm, g_mm);

    cudaFuncSetAttribute(gemm_mma<0>, cudaFuncAttributeMaxDynamicSharedMemorySize, GSMEM);
    cudaFuncSetAttribute(gemm_mma<1>, cudaFuncAttributeMaxDynamicSharedMemorySize, GSMEM);
    cudaFuncSetAttribute(attn_mma, cudaFuncAttributeMaxDynamicSharedMemorySize, ASMEM);

    // 1. xn = layernorm(x)
    ln_kernel<<<RR, 128>>>(x);
    // 2. mm = silu(xn @ uvqk)  [8192 x 2048, K=512]
    gemm_mma<0><<<dim3(NC / 128, RR / 128), 256, GSMEM>>>(
        (const float*)pxn, uvqk, (float*)pmm, nullptr, nullptr, NC, DD);
    // 3. attention
    attn_mma<<<dim3(NN / 64, HH, BB), 256, ASMEM>>>();
    // 4. o_input = u * layernorm(attn) -> g_xn
    gated_ln_kernel<<<RR, 128>>>();
    // 5. out = o_input @ o_weight^T + bias + x  [8192 x 512, K=512]
    gemm_mma<1><<<dim3(DD / 128, RR / 128), 256, GSMEM>>>(
        (const float*)pxn, ow, out, ob, x, DD, DD);
}